// round 4
// baseline (speedup 1.0000x reference)
#include <cuda_runtime.h>
#include <cuda_fp16.h>

#define CCH 16
#define GSZ 300

// fp16 channel-innermost scratch (allocation-free __device__ globals).
// +32 halves padding: clamped x1/z1 edge reads past last texel are in-bounds
// (weight is exactly 0 there, pad is zero-initialized .bss).
__device__ __half g_planes_h[3 * GSZ * GSZ * CCH + 32];  // [i][y][x][c], 8.64MB
__device__ __half g_lines_h[3 * GSZ * CCH + 32];         // [i][g][c]

struct alignas(16) Half8 { __half2 h[4]; };

// ---------------------------------------------------------------------------
// Transpose + quantize planes (3,C,G,G) fp32 -> (3,G,G,C) fp16.
// ---------------------------------------------------------------------------
__global__ void transpose_planes_kernel(const float* __restrict__ planes) {
    int idx = blockIdx.x * blockDim.x + threadIdx.x;
    if (idx >= 3 * GSZ * GSZ) return;
    int x  = idx % GSZ;
    int yi = idx / GSZ;
    int y  = yi % GSZ;
    int i  = yi / GSZ;

    const float* src = planes + ((size_t)i * CCH) * GSZ * GSZ + (size_t)y * GSZ + x;
    __half buf[CCH];
#pragma unroll
    for (int c = 0; c < CCH; c++)
        buf[c] = __float2half_rn(__ldg(src + (size_t)c * GSZ * GSZ));

    uint4* dst = reinterpret_cast<uint4*>(g_planes_h + (size_t)idx * CCH);
    const uint4* sp = reinterpret_cast<const uint4*>(buf);
    dst[0] = sp[0];
    dst[1] = sp[1];
}

// Transpose + quantize lines (3,C,G) -> (3,G,C) fp16
__global__ void transpose_lines_kernel(const float* __restrict__ lines) {
    int idx = blockIdx.x * blockDim.x + threadIdx.x;
    if (idx >= 3 * GSZ) return;
    int g = idx % GSZ;
    int i = idx / GSZ;

    __half buf[CCH];
#pragma unroll
    for (int c = 0; c < CCH; c++)
        buf[c] = __float2half_rn(__ldg(lines + ((size_t)i * CCH + c) * GSZ + g));

    uint4* dst = reinterpret_cast<uint4*>(g_lines_h + (size_t)idx * CCH);
    const uint4* sp = reinterpret_cast<const uint4*>(buf);
    dst[0] = sp[0];
    dst[1] = sp[1];
}

// ---------------------------------------------------------------------------
// Sampler: 4 lanes per point (lane = p*4 + r), 8 points/warp, 64 points/block.
// fp16 texel = 32B so the (x0,x1) bilinear pair is ONE contiguous 64B region:
// lane r loads 16B chunk r  ->  r<2 holds x0 ch[8r..], r>=2 holds x1 ch[..].
// x-combine with one shfl_xor(2)+add per value. Same trick for (z0,z1) lines.
// Outputs staged in smem (stride 53: conflict-free), then coalesced STG.
// ---------------------------------------------------------------------------
__global__ __launch_bounds__(256) void vm_sample_kernel(
        const float* __restrict__ xyz, float* __restrict__ out, int N) {
    __shared__ float s[64][53];

    int tid    = threadIdx.x;
    int warpId = tid >> 5;
    int lane   = tid & 31;
    int p = lane >> 2;        // point in warp (0..7)
    int r = lane & 3;         // 16B chunk of the 64B pair (0..3)

    int blockBase = blockIdx.x * 64;
    int wBase     = blockBase + warpId * 8;

    // Coalesced coord fetch: lanes 0..23 read 8 points * 3 coords
    float vld = 0.0f;
    {
        long long gi = (long long)wBase * 3 + lane;
        if (lane < 24 && gi < (long long)N * 3)
            vld = __ldg(xyz + gi);
    }
    float c0 = __shfl_sync(0xffffffffu, vld, p * 3 + 0);
    float c1 = __shfl_sync(0xffffffffu, vld, p * 3 + 1);
    float c2 = __shfl_sync(0xffffffffu, vld, p * 3 + 2);
    float coords[3] = {c0, c1, c2};   // 0 for tail points -> safe indices

    int   i0[3];
    float w[3];
#pragma unroll
    for (int d = 0; d < 3; d++) {
        float x  = (coords[d] + 1.0f) * 0.5f * (float)(GSZ - 1);
        float xf = floorf(x);
        xf = fminf(fmaxf(xf, 0.0f), (float)(GSZ - 1));
        i0[d] = (int)xf;
        w[d]  = x - xf;
    }

    // matMode = ((1,2),(0,2),(0,1))
    const int ma[3] = {1, 0, 0};
    const int mb[3] = {2, 2, 1};

    int  pt     = warpId * 8 + p;
    bool storer = (r < 2);

#pragma unroll
    for (int i = 0; i < 3; i++) {
        int a = ma[i], b = mb[i];
        int x0 = i0[a];
        int y0 = i0[b];
        int y1 = min(y0 + 1, GSZ - 1);
        int z0 = i0[i];
        float wx = w[a], wy = w[b], wz = w[i];

        // x-weight folded into row weights; r<2 carries x0, r>=2 carries x1.
        float wsel = (r < 2) ? (1.0f - wx) : wx;
        float wy0s = (1.0f - wy) * wsel;
        float wy1s = wy * wsel;
        float lsel = (r < 2) ? (1.0f - wz) : wz;

        const Half8* rowA = reinterpret_cast<const Half8*>(
            g_planes_h + ((size_t)(i * GSZ + y0) * GSZ + x0) * CCH) + r;
        const Half8* rowB = reinterpret_cast<const Half8*>(
            g_planes_h + ((size_t)(i * GSZ + y1) * GSZ + x0) * CCH) + r;
        const Half8* lp = reinterpret_cast<const Half8*>(
            g_lines_h + (size_t)(i * GSZ + z0) * CCH) + r;

        Half8 ha = *rowA;
        Half8 hb = *rowB;
        Half8 hl = *lp;

        float v[8], lv[8];
#pragma unroll
        for (int j = 0; j < 4; j++) {
            float2 fa = __half22float2(ha.h[j]);
            float2 fb = __half22float2(hb.h[j]);
            float2 fl = __half22float2(hl.h[j]);
            v[2 * j + 0]  = fa.x * wy0s + fb.x * wy1s;
            v[2 * j + 1]  = fa.y * wy0s + fb.y * wy1s;
            lv[2 * j + 0] = fl.x * lsel;
            lv[2 * j + 1] = fl.y * lsel;
        }
#pragma unroll
        for (int j = 0; j < 8; j++) {
            v[j]  += __shfl_xor_sync(0xffffffffu, v[j],  2);
            lv[j] += __shfl_xor_sync(0xffffffffu, lv[j], 2);
        }

        if (storer) {
            int cb = i * CCH + 8 * r;   // r=0: ch0-7, r=1: ch8-15
#pragma unroll
            for (int j = 0; j < 8; j++)
                s[pt][cb + j] = v[j] * lv[j];
        }
    }

    __syncthreads();

    // Coalesced writeout: 48 channels x 64 points = 12 x 256
#pragma unroll
    for (int k = 0; k < 12; k++) {
        int idx = k * 256 + tid;
        int c  = idx >> 6;        // 0..47
        int pp = idx & 63;
        int nn = blockBase + pp;
        if (nn < N)
            out[(size_t)c * N + nn] = s[pp][c];
    }
}

extern "C" void kernel_launch(void* const* d_in, const int* in_sizes, int n_in,
                              void* d_out, int out_size) {
    const float* xyz    = (const float*)d_in[0];
    const float* planes = (const float*)d_in[1];
    const float* lines  = (const float*)d_in[2];
    float* out = (float*)d_out;

    int N = in_sizes[0] / 3;

    {
        int total = 3 * GSZ * GSZ;
        int threads = 256;
        transpose_planes_kernel<<<(total + threads - 1) / threads, threads>>>(planes);
    }
    {
        int total = 3 * GSZ;
        int threads = 256;
        transpose_lines_kernel<<<(total + threads - 1) / threads, threads>>>(lines);
    }
    {
        int blocks = (N + 63) / 64;   // 64 points per 256-thread block
        vm_sample_kernel<<<blocks, 256>>>(xyz, out, N);
    }
}

// round 5
// speedup vs baseline: 1.2926x; 1.2926x over previous
#include <cuda_runtime.h>
#include <cuda_fp16.h>

#define CCH 16
#define GSZ 300

// Pair-interleaved fp16 scratch (allocation-free __device__ globals).
// Planes: Pd[i][y][x][c][yp] - 64B entry = 16 channels x (y, y+1) pair.
// Lines:  Ld[i][g][c][zp]    - 64B entry = 16 channels x (z, z+1) pair.
// y+1 / z+1 clamped at build time, so the sampler needs NO second row fetch.
__device__ __half g_planes_d[(size_t)3 * GSZ * GSZ * CCH * 2];  // 17.28 MB
__device__ __half g_lines_d[3 * GSZ * CCH * 2];                 // 115 KB

struct alignas(16) Half8 { __half2 h[4]; };

// ---------------------------------------------------------------------------
// Build plane entries: (3,C,G,G) fp32 -> (3,G,G,C,2) fp16 with y-pair.
// ---------------------------------------------------------------------------
__global__ void build_planes_kernel(const float* __restrict__ planes) {
    int idx = blockIdx.x * blockDim.x + threadIdx.x;     // over 3*G*G entries
    if (idx >= 3 * GSZ * GSZ) return;
    int x  = idx % GSZ;
    int yi = idx / GSZ;
    int y  = yi % GSZ;
    int i  = yi / GSZ;
    int y1 = min(y + 1, GSZ - 1);

    const float* s0 = planes + ((size_t)i * CCH) * GSZ * GSZ + (size_t)y  * GSZ + x;
    const float* s1 = planes + ((size_t)i * CCH) * GSZ * GSZ + (size_t)y1 * GSZ + x;

    __half buf[2 * CCH];
#pragma unroll
    for (int c = 0; c < CCH; c++) {
        buf[2 * c + 0] = __float2half_rn(__ldg(s0 + (size_t)c * GSZ * GSZ));
        buf[2 * c + 1] = __float2half_rn(__ldg(s1 + (size_t)c * GSZ * GSZ));
    }

    uint4* dst = reinterpret_cast<uint4*>(g_planes_d + (size_t)idx * 2 * CCH);
    const uint4* sp = reinterpret_cast<const uint4*>(buf);
#pragma unroll
    for (int k = 0; k < 4; k++) dst[k] = sp[k];
}

// Build line entries: (3,C,G) fp32 -> (3,G,C,2) fp16 with z-pair.
__global__ void build_lines_kernel(const float* __restrict__ lines) {
    int idx = blockIdx.x * blockDim.x + threadIdx.x;     // over 3*G entries
    if (idx >= 3 * GSZ) return;
    int g  = idx % GSZ;
    int i  = idx / GSZ;
    int g1 = min(g + 1, GSZ - 1);

    __half buf[2 * CCH];
#pragma unroll
    for (int c = 0; c < CCH; c++) {
        buf[2 * c + 0] = __float2half_rn(__ldg(lines + ((size_t)i * CCH + c) * GSZ + g));
        buf[2 * c + 1] = __float2half_rn(__ldg(lines + ((size_t)i * CCH + c) * GSZ + g1));
    }

    uint4* dst = reinterpret_cast<uint4*>(g_lines_d + (size_t)idx * 2 * CCH);
    const uint4* sp = reinterpret_cast<const uint4*>(buf);
#pragma unroll
    for (int k = 0; k < 4; k++) dst[k] = sp[k];
}

// ---------------------------------------------------------------------------
// Sampler: 4 lanes/point (lane = p*4 + r), 8 points/warp — R2 skeleton.
// Lane r owns channels 4r..4r+3. One 16B chunk of a pair-entry gives BOTH
// y-texels (or z-texels) for those channels -> 2 plane gathers + 1 line
// gather per mode per lane, no shfl, no smem.
// ---------------------------------------------------------------------------
__global__ __launch_bounds__(256) void vm_sample_kernel(
        const float* __restrict__ xyz, float* __restrict__ out, int N) {
    int warpGlobal = (blockIdx.x * blockDim.x + threadIdx.x) >> 5;
    int lane = threadIdx.x & 31;
    int p = lane >> 2;          // point within warp (0..7)
    int r = lane & 3;           // channel quad (0..3)
    int base = warpGlobal * 8;
    if (base >= N) return;

    // Coalesced coord fetch: first 24 lanes read xyz[base*3 .. base*3+23]
    float v = 0.0f;
    {
        long long gi = (long long)base * 3 + lane;
        if (lane < 24 && gi < (long long)N * 3)
            v = __ldg(xyz + gi);
    }
    float c0 = __shfl_sync(0xffffffffu, v, p * 3 + 0);
    float c1 = __shfl_sync(0xffffffffu, v, p * 3 + 1);
    float c2 = __shfl_sync(0xffffffffu, v, p * 3 + 2);

    int n = base + p;
    if (n >= N) return;

    float coords[3] = {c0, c1, c2};
    int   i0[3];
    float w[3];
#pragma unroll
    for (int d = 0; d < 3; d++) {
        float x  = (coords[d] + 1.0f) * 0.5f * (float)(GSZ - 1);
        float xf = floorf(x);
        xf = fminf(fmaxf(xf, 0.0f), (float)(GSZ - 1));
        i0[d] = (int)xf;
        w[d]  = x - xf;
    }

    // matMode = ((1,2),(0,2),(0,1))
    const int ma[3] = {1, 0, 0};
    const int mb[3] = {2, 2, 1};

#pragma unroll
    for (int i = 0; i < 3; i++) {
        int a = ma[i], b = mb[i];
        int x0 = i0[a];
        int x1 = min(x0 + 1, GSZ - 1);
        int y0 = i0[b];
        int z0 = i0[i];
        float wx = w[a], wy = w[b], wz = w[i];
        float wy0 = 1.0f - wy;
        float wz0 = 1.0f - wz;
        float wx0 = 1.0f - wx;

        size_t rowBase = ((size_t)(i * GSZ + y0) * GSZ) * (2 * CCH);
        const Half8* eA = reinterpret_cast<const Half8*>(
            g_planes_d + rowBase + (size_t)x0 * (2 * CCH) + r * 8);
        const Half8* eB = reinterpret_cast<const Half8*>(
            g_planes_d + rowBase + (size_t)x1 * (2 * CCH) + r * 8);
        const Half8* eL = reinterpret_cast<const Half8*>(
            g_lines_d + (size_t)(i * GSZ + z0) * (2 * CCH) + r * 8);

        Half8 hA = *eA;   // ch j: (y0, y1) at x0
        Half8 hB = *eB;   // ch j: (y0, y1) at x1
        Half8 hL = *eL;   // ch j: (z0, z1)

#pragma unroll
        for (int j = 0; j < 4; j++) {
            float2 fa = __half22float2(hA.h[j]);
            float2 fb = __half22float2(hB.h[j]);
            float2 fl = __half22float2(hL.h[j]);

            float vA = fa.x * wy0 + fa.y * wy;   // x0 column
            float vB = fb.x * wy0 + fb.y * wy;   // x1 column
            float pv = vA * wx0 + vB * wx;
            float lv = fl.x * wz0 + fl.y * wz;

            out[(size_t)(i * CCH + 4 * r + j) * N + n] = pv * lv;
        }
    }
}

extern "C" void kernel_launch(void* const* d_in, const int* in_sizes, int n_in,
                              void* d_out, int out_size) {
    const float* xyz    = (const float*)d_in[0];
    const float* planes = (const float*)d_in[1];
    const float* lines  = (const float*)d_in[2];
    float* out = (float*)d_out;

    int N = in_sizes[0] / 3;

    {
        int total = 3 * GSZ * GSZ;
        int threads = 256;
        build_planes_kernel<<<(total + threads - 1) / threads, threads>>>(planes);
    }
    {
        int total = 3 * GSZ;
        int threads = 256;
        build_lines_kernel<<<(total + threads - 1) / threads, threads>>>(lines);
    }
    {
        // 4 lanes per point, 8 points per warp
        long long totalThreads = (long long)((N + 7) / 8) * 32;
        int threads = 256;
        long long blocks = (totalThreads + threads - 1) / threads;
        vm_sample_kernel<<<(int)blocks, threads>>>(xyz, out, N);
    }
}